// round 12
// baseline (speedup 1.0000x reference)
#include <cuda_runtime.h>
#include <cstddef>

// Problem constants (fixed by setup_inputs)
constexpr int B = 8;
constexpr int C = 144;
constexpr int N = 4096;
constexpr int K = 16;
constexpr int G = 9;
constexpr int D = 16;          // C / G
constexpr int NTILE = 64;      // points per transpose block
constexpr int NBLK_N = N / NTILE;

constexpr int FEAT_ELEMS = B * C * N;      // 4718592
constexpr int CENT_ELEMS = B * G * N;      // 294912
constexpr int IDX_ELEMS  = B * N * K;      // 524288
constexpr int TBLOCKS    = B * G * NBLK_N; // 4608 (= CENT_ELEMS / 64)

constexpr int PTS     = 32;                // points per attn block (8 lanes each)
constexpr int NBLK_A  = N / PTS;           // 128
constexpr int ABLOCKS = B * G * NBLK_A;    // 9216

// Fused scratch: per point one 128B row = [key(16 floats) | value(16 floats)].
__device__ __align__(128) float g_qkv[(size_t)B * G * N * 32];

// Index-dtype flag: 1 if idx_knn is int64, 0 if int32.
__device__ int g_idx_is64;

// ---------------------------------------------------------------------------
// Transpose (B, C, N) -> fused (B*G, N, 32) rows, zero the centrality region,
// and (block 0 only) detect the idx dtype.
// ---------------------------------------------------------------------------
__global__ void __launch_bounds__(256) transpose_kernel(
    const float* __restrict__ qk, const float* __restrict__ val,
    const unsigned int* __restrict__ idx_raw,
    float* __restrict__ cent)
{
    __shared__ float tile[D][NTILE + 1];
    __shared__ unsigned int s_any;

    const int blk   = blockIdx.x;
    const int ntile = blk % NBLK_N;
    const int bg    = blk / NBLK_N;
    const int g     = bg % G;
    const int b     = bg / G;
    const int n0    = ntile * NTILE;
    const int tid   = threadIdx.x;

    // ---- block 0: idx dtype detection (odd words all zero => int64) ----
    if (blk == 0) {
        if (tid == 0) s_any = 0u;
        __syncthreads();
        unsigned int v = idx_raw[2 * tid + 1] |
                         idx_raw[2 * (tid + 256) + 1] |
                         idx_raw[2 * (tid + 512) + 1] |
                         idx_raw[2 * (tid + 768) + 1];
        if (v) atomicOr(&s_any, 1u);
        __syncthreads();
        if (tid == 0) g_idx_is64 = (s_any == 0u) ? 1 : 0;
    }

    // ---- zero this block's 64-element slice of centrality ----
    if (cent != nullptr && tid < 64)
        cent[(size_t)blk * 64 + tid] = 0.0f;

    const size_t src_off = ((size_t)b * C + (size_t)g * D) * N + n0;
    float* dst = g_qkv + ((size_t)bg * N + n0) * 32;

    {   // queryandkey -> row offset [0:16)
        const float* src = qk + src_off;
        #pragma unroll
        for (int r = 0; r < 4; r++) {
            int e = tid + r * 256;
            int j = e >> 6, nn = e & 63;
            tile[j][nn] = src[(size_t)j * N + nn];
        }
        __syncthreads();
        #pragma unroll
        for (int r = 0; r < 4; r++) {
            int e = tid + r * 256;
            int nn = e >> 4, j = e & 15;
            dst[nn * 32 + j] = tile[j][nn];
        }
        __syncthreads();
    }
    {   // value -> row offset [16:32)
        const float* src = val + src_off;
        #pragma unroll
        for (int r = 0; r < 4; r++) {
            int e = tid + r * 256;
            int j = e >> 6, nn = e & 63;
            tile[j][nn] = src[(size_t)j * N + nn];
        }
        __syncthreads();
        #pragma unroll
        for (int r = 0; r < 4; r++) {
            int e = tid + r * 256;
            int nn = e >> 4, j = e & 15;
            dst[nn * 32 + 16 + j] = tile[j][nn];
        }
    }
}

// ---------------------------------------------------------------------------
// Fused attention. 8 lanes per point: lanes 0-3 carry key channels, lanes 4-7
// carry value channels; one 128B gather per (point, neighbor) fetches both.
// Dot reduction: zero value-lane partials, then 3 butterfly shuffles
// (xor1, xor2, xor4) deliver the dot to all 8 lanes (no broadcast shuffle).
// Gather addressing: smem holds pre-scaled BYTE offsets (m << 7); per-k
// address math is a single pointer add.
// Softmax shifted by the first logit (shift-invariant, no max pre-pass).
// ---------------------------------------------------------------------------
__global__ void __launch_bounds__(256, 6) attn_kernel(
    const void* __restrict__ idx_raw,
    float* __restrict__ out,           // feature region
    float* __restrict__ cent)          // centrality region (may be null)
{
    __shared__ int   s_off[PTS][17];    // [point][k]: neighbor byte offsets
    __shared__ float ftile[PTS][D + 1];

    const int blk = blockIdx.x;
    const int nt  = blk % NBLK_A;
    const int bg  = blk / NBLK_A;
    const int g   = bg % G;
    const int b   = bg / G;
    const int n0  = nt * PTS;

    const int tid = threadIdx.x;
    const int p   = tid >> 3;           // point within block (0..31)
    const int L   = tid & 7;            // lane within point (0..7)
    const int n   = n0 + p;
    const unsigned FULL = 0xffffffffu;

    const float keysel = (L < 4) ? 1.0f : 0.0f;   // value lanes contribute 0

    const size_t bgN = (size_t)bg * N;

    // --- lane L loads neighbors 2L, 2L+1 (dtype-dispatched), clamp ---
    const size_t ibase = ((size_t)b * N + n) * K + 2 * L;
    int i0, i1;
    if (g_idx_is64) {
        longlong2 e = *reinterpret_cast<const longlong2*>(
            reinterpret_cast<const long long*>(idx_raw) + ibase);
        i0 = (int)e.x; i1 = (int)e.y;
    } else {
        int2 e = *reinterpret_cast<const int2*>(
            reinterpret_cast<const int*>(idx_raw) + ibase);
        i0 = e.x; i1 = e.y;
    }
    i0 = min(max(i0, 0), N - 1);
    i1 = min(max(i1, 0), N - 1);
    s_off[p][2 * L]     = i0 << 7;      // 128 bytes per point row
    s_off[p][2 * L + 1] = i1 << 7;
    __syncwarp();

    // Gather base pointer: folds bg-slab and this lane's 16B sub-offset.
    const char* gbase = reinterpret_cast<const char*>(g_qkv)
                      + bgN * 128 + (size_t)L * 16;

    // --- query (key-part of own row; lanes 4-7 duplicate lanes 0-3) ---
    const float4 q = *reinterpret_cast<const float4*>(
        reinterpret_cast<const char*>(g_qkv) + (bgN + n) * 128 + (size_t)(L & 3) * 16);

    // --- single pass: gather kv row, logit, exp-accumulate value ---
    float s0 = 0.0f;                    // shift = first logit
    float sum = 0.0f;
    float my_e0 = 0.0f, my_e1 = 0.0f;   // exps of this lane's own 2 neighbors
    float4 acc = make_float4(0.f, 0.f, 0.f, 0.f);

    #pragma unroll
    for (int k = 0; k < 16; k++) {
        int off = s_off[p][k];          // broadcast LDS (pre-scaled bytes)
        float4 kv = *reinterpret_cast<const float4*>(gbase + off);
        // partial dot: key lanes only; butterfly-reduce across all 8 lanes
        float s = fmaf(q.x, kv.x, fmaf(q.y, kv.y, fmaf(q.z, kv.z, q.w * kv.w)));
        s *= keysel;
        s += __shfl_xor_sync(FULL, s, 1);
        s += __shfl_xor_sync(FULL, s, 2);
        s += __shfl_xor_sync(FULL, s, 4);             // all 8 lanes: full dot
        if (k == 0) s0 = s;
        float e = __expf(s - s0);       // e = 1 for k == 0
        if (2 * L == k)     my_e0 = e;  // compile-time k: ISETP + SEL
        if (2 * L + 1 == k) my_e1 = e;
        sum += e;
        acc.x = fmaf(e, kv.x, acc.x);   // value channels live in lanes 4-7
        acc.y = fmaf(e, kv.y, acc.y);
        acc.z = fmaf(e, kv.z, acc.z);
        acc.w = fmaf(e, kv.w, acc.w);
    }
    const float inv = 1.0f / sum;

    // --- centrality: lane L owns neighbors 2L, 2L+1 ---
    if (cent != nullptr) {
        atomicAdd(&cent[bgN + (size_t)i0], my_e0 * inv);
        atomicAdd(&cent[bgN + (size_t)i1], my_e1 * inv);
    }

    // --- feature: lanes 4-7 hold the value accumulation ---
    if (L >= 4) {
        int c0 = (L - 4) * 4;
        ftile[p][c0 + 0] = acc.x * inv;
        ftile[p][c0 + 1] = acc.y * inv;
        ftile[p][c0 + 2] = acc.z * inv;
        ftile[p][c0 + 3] = acc.w * inv;
    }
    __syncthreads();

    // --- coalesced write in (B, C, N) layout: 16 rows x 32 points ---
    float* fout = out + ((size_t)b * C + (size_t)g * D) * N + n0;
    #pragma unroll
    for (int r = 0; r < 2; r++) {
        int e = tid + r * 256;
        int j = e >> 5, nn = e & 31;
        fout[(size_t)j * N + nn] = ftile[nn][j];
    }
}

// ---------------------------------------------------------------------------
// Launch
// ---------------------------------------------------------------------------
extern "C" void kernel_launch(void* const* d_in, const int* in_sizes, int n_in,
                              void* d_out, int out_size)
{
    // Resolve inputs by element count (robust to ordering)
    const float* qk  = nullptr;
    const float* val = nullptr;
    const void*  idx = nullptr;

    for (int i = 0; i < n_in; i++) {
        if (in_sizes[i] == FEAT_ELEMS) {
            if (qk == nullptr)       qk  = (const float*)d_in[i];
            else if (val == nullptr) val = (const float*)d_in[i];
        } else if (in_sizes[i] == IDX_ELEMS) {
            idx = d_in[i];
        }
    }
    if (qk == nullptr || val == nullptr || idx == nullptr) {
        qk  = (const float*)d_in[4];
        val = (const float*)d_in[5];
        idx = d_in[6];
    }

    float* out  = (float*)d_out;                   // feature (B*C*N) first
    float* cent = nullptr;                         // then centrality (B*G*N)
    if (out_size >= FEAT_ELEMS + CENT_ELEMS)
        cent = out + (size_t)FEAT_ELEMS;

    transpose_kernel<<<TBLOCKS, 256>>>(qk, val, (const unsigned int*)idx, cent);
    attn_kernel<<<ABLOCKS, 256>>>(idx, out, cent);
}

// round 13
// speedup vs baseline: 1.0776x; 1.0776x over previous
#include <cuda_runtime.h>
#include <cstddef>

// Problem constants (fixed by setup_inputs)
constexpr int B = 8;
constexpr int C = 144;
constexpr int N = 4096;
constexpr int K = 16;
constexpr int G = 9;
constexpr int D = 16;          // C / G
constexpr int NTILE = 64;      // points per transpose block
constexpr int NBLK_N = N / NTILE;

constexpr int FEAT_ELEMS = B * C * N;      // 4718592
constexpr int CENT_ELEMS = B * G * N;      // 294912
constexpr int IDX_ELEMS  = B * N * K;      // 524288
constexpr int TBLOCKS    = B * G * NBLK_N; // 4608 (= CENT_ELEMS / 64)

constexpr int PTS     = 32;                // points per attn block (8 lanes each)
constexpr int NBLK_A  = N / PTS;           // 128
constexpr int ABLOCKS = B * G * NBLK_A;    // 9216

// Fused scratch: per point one 128B row = [key(16 floats) | value(16 floats)].
__device__ __align__(128) float g_qkv[(size_t)B * G * N * 32];

// Index-dtype flag: 1 if idx_knn is int64, 0 if int32.
__device__ int g_idx_is64;

// ---------------------------------------------------------------------------
// Transpose (B, C, N) -> fused (B*G, N, 32) rows, zero the centrality region,
// and (block 0 only) detect the idx dtype.
// ---------------------------------------------------------------------------
__global__ void __launch_bounds__(256) transpose_kernel(
    const float* __restrict__ qk, const float* __restrict__ val,
    const unsigned int* __restrict__ idx_raw,
    float* __restrict__ cent)
{
    __shared__ float tile[D][NTILE + 1];
    __shared__ unsigned int s_any;

    const int blk   = blockIdx.x;
    const int ntile = blk % NBLK_N;
    const int bg    = blk / NBLK_N;
    const int g     = bg % G;
    const int b     = bg / G;
    const int n0    = ntile * NTILE;
    const int tid   = threadIdx.x;

    // ---- block 0: idx dtype detection (odd words all zero => int64) ----
    if (blk == 0) {
        if (tid == 0) s_any = 0u;
        __syncthreads();
        unsigned int v = idx_raw[2 * tid + 1] |
                         idx_raw[2 * (tid + 256) + 1] |
                         idx_raw[2 * (tid + 512) + 1] |
                         idx_raw[2 * (tid + 768) + 1];
        if (v) atomicOr(&s_any, 1u);
        __syncthreads();
        if (tid == 0) g_idx_is64 = (s_any == 0u) ? 1 : 0;
    }

    // ---- zero this block's 64-element slice of centrality ----
    if (cent != nullptr && tid < 64)
        cent[(size_t)blk * 64 + tid] = 0.0f;

    const size_t src_off = ((size_t)b * C + (size_t)g * D) * N + n0;
    float* dst = g_qkv + ((size_t)bg * N + n0) * 32;

    {   // queryandkey -> row offset [0:16)
        const float* src = qk + src_off;
        #pragma unroll
        for (int r = 0; r < 4; r++) {
            int e = tid + r * 256;
            int j = e >> 6, nn = e & 63;
            tile[j][nn] = src[(size_t)j * N + nn];
        }
        __syncthreads();
        #pragma unroll
        for (int r = 0; r < 4; r++) {
            int e = tid + r * 256;
            int nn = e >> 4, j = e & 15;
            dst[nn * 32 + j] = tile[j][nn];
        }
        __syncthreads();
    }
    {   // value -> row offset [16:32)
        const float* src = val + src_off;
        #pragma unroll
        for (int r = 0; r < 4; r++) {
            int e = tid + r * 256;
            int j = e >> 6, nn = e & 63;
            tile[j][nn] = src[(size_t)j * N + nn];
        }
        __syncthreads();
        #pragma unroll
        for (int r = 0; r < 4; r++) {
            int e = tid + r * 256;
            int nn = e >> 4, j = e & 15;
            dst[nn * 32 + 16 + j] = tile[j][nn];
        }
    }
}

// ---------------------------------------------------------------------------
// Fused attention. 8 lanes per point: lanes 0-3 carry key channels, lanes 4-7
// carry value channels; one 128B gather per (point, neighbor) fetches both.
// Gathers are software-pipelined at depth 3 (loads for k+1, k+2 in flight
// while k is processed) — R12 showed ptxas won't keep MLP up on its own when
// register-squeezed, so the 4-block bound restores the budget and the
// pipeline spends it on outstanding loads.
// ---------------------------------------------------------------------------
__global__ void __launch_bounds__(256, 4) attn_kernel(
    const void* __restrict__ idx_raw,
    float* __restrict__ out,           // feature region
    float* __restrict__ cent)          // centrality region (may be null)
{
    __shared__ int   s_off[PTS][17];    // [point][k]: neighbor byte offsets
    __shared__ float ftile[PTS][D + 1];

    const int blk = blockIdx.x;
    const int nt  = blk % NBLK_A;
    const int bg  = blk / NBLK_A;
    const int g   = bg % G;
    const int b   = bg / G;
    const int n0  = nt * PTS;

    const int tid = threadIdx.x;
    const int p   = tid >> 3;           // point within block (0..31)
    const int L   = tid & 7;            // lane within point (0..7)
    const int n   = n0 + p;
    const unsigned FULL = 0xffffffffu;

    const float keysel = (L < 4) ? 1.0f : 0.0f;   // value lanes contribute 0

    const size_t bgN = (size_t)bg * N;

    // --- lane L loads neighbors 2L, 2L+1 (dtype-dispatched), clamp ---
    const size_t ibase = ((size_t)b * N + n) * K + 2 * L;
    int i0, i1;
    if (g_idx_is64) {
        longlong2 e = *reinterpret_cast<const longlong2*>(
            reinterpret_cast<const long long*>(idx_raw) + ibase);
        i0 = (int)e.x; i1 = (int)e.y;
    } else {
        int2 e = *reinterpret_cast<const int2*>(
            reinterpret_cast<const int*>(idx_raw) + ibase);
        i0 = e.x; i1 = e.y;
    }
    i0 = min(max(i0, 0), N - 1);
    i1 = min(max(i1, 0), N - 1);
    s_off[p][2 * L]     = i0 << 7;      // 128 bytes per point row
    s_off[p][2 * L + 1] = i1 << 7;
    __syncwarp();

    // Gather base pointer: folds bg-slab and this lane's 16B sub-offset.
    const char* gbase = reinterpret_cast<const char*>(g_qkv)
                      + bgN * 128 + (size_t)L * 16;

    // --- query (key-part of own row; lanes 4-7 duplicate lanes 0-3) ---
    const float4 q = *reinterpret_cast<const float4*>(
        reinterpret_cast<const char*>(g_qkv) + (bgN + n) * 128 + (size_t)(L & 3) * 16);

    // --- single pass, depth-3 pipelined gathers ---
    float s0 = 0.0f;                    // shift = first logit
    float sum = 0.0f;
    float my_e0 = 0.0f, my_e1 = 0.0f;   // exps of this lane's own 2 neighbors
    float4 acc = make_float4(0.f, 0.f, 0.f, 0.f);

    float4 kv_a = *reinterpret_cast<const float4*>(gbase + s_off[p][0]);
    float4 kv_b = *reinterpret_cast<const float4*>(gbase + s_off[p][1]);

    #pragma unroll
    for (int k = 0; k < 16; k++) {
        float4 kv = kv_a;
        kv_a = kv_b;
        if (k + 2 < 16)
            kv_b = *reinterpret_cast<const float4*>(gbase + s_off[p][k + 2]);

        // partial dot: key lanes only; butterfly-reduce across all 8 lanes
        float s = fmaf(q.x, kv.x, fmaf(q.y, kv.y, fmaf(q.z, kv.z, q.w * kv.w)));
        s *= keysel;
        s += __shfl_xor_sync(FULL, s, 1);
        s += __shfl_xor_sync(FULL, s, 2);
        s += __shfl_xor_sync(FULL, s, 4);             // all 8 lanes: full dot
        if (k == 0) s0 = s;
        float e = __expf(s - s0);       // e = 1 for k == 0
        if (2 * L == k)     my_e0 = e;  // compile-time k: ISETP + SEL
        if (2 * L + 1 == k) my_e1 = e;
        sum += e;
        acc.x = fmaf(e, kv.x, acc.x);   // value channels live in lanes 4-7
        acc.y = fmaf(e, kv.y, acc.y);
        acc.z = fmaf(e, kv.z, acc.z);
        acc.w = fmaf(e, kv.w, acc.w);
    }
    const float inv = 1.0f / sum;

    // --- centrality: lane L owns neighbors 2L, 2L+1 ---
    if (cent != nullptr) {
        atomicAdd(&cent[bgN + (size_t)i0], my_e0 * inv);
        atomicAdd(&cent[bgN + (size_t)i1], my_e1 * inv);
    }

    // --- feature: lanes 4-7 hold the value accumulation ---
    if (L >= 4) {
        int c0 = (L - 4) * 4;
        ftile[p][c0 + 0] = acc.x * inv;
        ftile[p][c0 + 1] = acc.y * inv;
        ftile[p][c0 + 2] = acc.z * inv;
        ftile[p][c0 + 3] = acc.w * inv;
    }
    __syncthreads();

    // --- coalesced write in (B, C, N) layout: 16 rows x 32 points ---
    float* fout = out + ((size_t)b * C + (size_t)g * D) * N + n0;
    #pragma unroll
    for (int r = 0; r < 2; r++) {
        int e = tid + r * 256;
        int j = e >> 5, nn = e & 31;
        fout[(size_t)j * N + nn] = ftile[nn][j];
    }
}

// ---------------------------------------------------------------------------
// Launch
// ---------------------------------------------------------------------------
extern "C" void kernel_launch(void* const* d_in, const int* in_sizes, int n_in,
                              void* d_out, int out_size)
{
    // Resolve inputs by element count (robust to ordering)
    const float* qk  = nullptr;
    const float* val = nullptr;
    const void*  idx = nullptr;

    for (int i = 0; i < n_in; i++) {
        if (in_sizes[i] == FEAT_ELEMS) {
            if (qk == nullptr)       qk  = (const float*)d_in[i];
            else if (val == nullptr) val = (const float*)d_in[i];
        } else if (in_sizes[i] == IDX_ELEMS) {
            idx = d_in[i];
        }
    }
    if (qk == nullptr || val == nullptr || idx == nullptr) {
        qk  = (const float*)d_in[4];
        val = (const float*)d_in[5];
        idx = d_in[6];
    }

    float* out  = (float*)d_out;                   // feature (B*C*N) first
    float* cent = nullptr;                         // then centrality (B*G*N)
    if (out_size >= FEAT_ELEMS + CENT_ELEMS)
        cent = out + (size_t)FEAT_ELEMS;

    transpose_kernel<<<TBLOCKS, 256>>>(qk, val, (const unsigned int*)idx, cent);
    attn_kernel<<<ABLOCKS, 256>>>(idx, out, cent);
}